// round 6
// baseline (speedup 1.0000x reference)
#include <cuda_runtime.h>

typedef unsigned long long u64;
#define DINL __device__ __forceinline__

DINL u64 pack2(float lo, float hi) {
    u64 r;
    asm("mov.b64 %0, {%1, %2};" : "=l"(r) : "r"(__float_as_uint(lo)), "r"(__float_as_uint(hi)));
    return r;
}
DINL void unpack2(u64 v, float& lo, float& hi) {
    unsigned int a, b;
    asm("mov.b64 {%0, %1}, %2;" : "=r"(a), "=r"(b) : "l"(v));
    lo = __uint_as_float(a);
    hi = __uint_as_float(b);
}
DINL u64 fma2(u64 a, u64 b, u64 c) {
    u64 d;
    asm("fma.rn.f32x2 %0, %1, %2, %3;" : "=l"(d) : "l"(a), "l"(b), "l"(c));
    return d;
}
DINL u64 add2(u64 a, u64 b) {
    u64 d;
    asm("add.rn.f32x2 %0, %1, %2;" : "=l"(d) : "l"(a), "l"(b));
    return d;
}

// Shapes: B=2, N=256, N1=N2=128, C=Co=16.
// h[b,n,j,k,o] = relu(base[b,n,o] + U[b,j,o] + V[b,k,o])
//   base = x.(Wa-Wb-Wc) + b1 ;  U = x1.Wb ;  V = x2.Wc
// h2 = relu(h @ W2 + b2); out = concat(max_{j,k} h2[:,:8], mean_{j,k} h2[:,8:])
//
// Block = one (b,n). Warp w owns j in [16w,16w+16). Lane owns k-quad
// {l, l+32, l+64, l+96}. Accumulators packed over k (f32x2): zA[p]={k0,k1},
// zB[p]={k2,k3} — 64 regs. Pack-over-k means t needs NO duplication (V is
// loaded as natural pairs); W2/U/b2 are stored pre-duplicated in SMEM.

__global__ void __launch_bounds__(256, 2)
ppr3_kernel(const float* __restrict__ x, const float* __restrict__ x1,
            const float* __restrict__ x2, const float* __restrict__ W1,
            const float* __restrict__ b1, const float* __restrict__ W2,
            const float* __restrict__ b2, float* __restrict__ out)
{
    __shared__ __align__(16) u64        sUd[128][16];  // {u,u} base+U dup'd (16 KB)
    __shared__ __align__(16) ulonglong2 sV2[16][32];   // [o][l] = {pack(v_l,v_l32), pack(v_l64,v_l96)} (8 KB)
    __shared__ __align__(16) u64        sW2d[16][16];  // [o][p] = {w,w} (2 KB)
    __shared__ __align__(16) u64        sB2d[16];      // {b2,b2}
    __shared__ float sBase[16];
    __shared__ float sRed[8][16];

    const int bx   = blockIdx.x;     // b*256 + n
    const int b    = bx >> 8;
    const int tid  = threadIdx.x;
    const int lane = tid & 31;
    const int w    = tid >> 5;

    // ---------------- setup phase 1 ----------------
    {   // W2 duplicated: all 256 threads, one entry each
        int o = tid >> 4, p = tid & 15;
        float wv = W2[o * 16 + p];
        sW2d[o][p] = pack2(wv, wv);
    }
    if (tid < 16) {
        int o = tid;
        sB2d[o] = pack2(b2[o], b2[o]);
        float s = b1[o];
        const float* xr = x + bx * 16;
        #pragma unroll
        for (int c = 0; c < 16; c++)
            s += xr[c] * (W1[c * 16 + o] - W1[(16 + c) * 16 + o] - W1[(32 + c) * 16 + o]);
        sBase[o] = s;
    }

    // V quads: [o][l] covers k = {l, l+32, l+64, l+96}
    {
        const float* x2b = x2 + b * 2048;
        for (int idx = tid; idx < 512; idx += 256) {
            int o = idx >> 5, l = idx & 31;
            const float* r0 = x2b + l * 16;
            const float* r1 = x2b + (l + 32) * 16;
            const float* r2 = x2b + (l + 64) * 16;
            const float* r3 = x2b + (l + 96) * 16;
            float s0 = 0.f, s1 = 0.f, s2 = 0.f, s3 = 0.f;
            #pragma unroll
            for (int c = 0; c < 16; c++) {
                float wv = W1[(32 + c) * 16 + o];
                s0 += r0[c] * wv; s1 += r1[c] * wv;
                s2 += r2[c] * wv; s3 += r3[c] * wv;
            }
            ulonglong2 q;
            q.x = pack2(s0, s1);
            q.y = pack2(s2, s3);
            sV2[o][l] = q;
        }
    }
    __syncthreads();

    // ---------------- setup phase 2: U (needs sBase) ----------------
    {
        const float* x1b = x1 + b * 2048;
        for (int idx = tid; idx < 2048; idx += 256) {
            int j = idx >> 4, o = idx & 15;
            float s = sBase[o];
            const float* xr = x1b + j * 16;
            #pragma unroll
            for (int c = 0; c < 16; c++) s += xr[c] * W1[(16 + c) * 16 + o];
            sUd[j][o] = pack2(s, s);
        }
    }
    __syncthreads();

    // ---------------- main loop ----------------
    float mx[8], sv[8];
    #pragma unroll
    for (int p = 0; p < 8; p++) { mx[p] = 0.f; sv[p] = 0.f; }  // relu(max)=max(0,..)

    #pragma unroll 1
    for (int jj = 0; jj < 16; jj++) {
        const u64* uj = sUd[(w << 4) + jj];

        u64 zA[16], zB[16];
        #pragma unroll
        for (int p = 0; p < 16; p++) {
            u64 t = sB2d[p];
            zA[p] = t; zB[p] = t;
        }

        #pragma unroll 1
        for (int o = 0; o < 16; o++) {
            u64 ud = uj[o];                       // LDS.64 broadcast
            ulonglong2 vq = sV2[o][lane];         // LDS.128, conflict-free
            u64 sA = add2(ud, vq.x);              // {u+v0, u+v1}
            u64 sB = add2(ud, vq.y);              // {u+v2, u+v3}
            float a0, a1, c0, c1;
            unpack2(sA, a0, a1);
            unpack2(sB, c0, c1);
            u64 tA = pack2(fmaxf(a0, 0.f), fmaxf(a1, 0.f));
            u64 tB = pack2(fmaxf(c0, 0.f), fmaxf(c1, 0.f));

            const ulonglong2* wr = reinterpret_cast<const ulonglong2*>(sW2d[o]);
            #pragma unroll
            for (int q = 0; q < 8; q++) {
                ulonglong2 wq = wr[q];            // LDS.128 broadcast, {w,w} pairs
                int p = 2 * q;
                zA[p]     = fma2(tA, wq.x, zA[p]);
                zB[p]     = fma2(tB, wq.x, zB[p]);
                zA[p + 1] = fma2(tA, wq.y, zA[p + 1]);
                zB[p + 1] = fma2(tB, wq.y, zB[p + 1]);
            }
        }

        // epilogue: p<8 -> max pool; p>=8 -> sum of relu
        #pragma unroll
        for (int p = 0; p < 8; p++) {
            float a, c, e, f;
            unpack2(zA[p], a, c);
            unpack2(zB[p], e, f);
            mx[p] = fmaxf(mx[p], fmaxf(fmaxf(a, c), fmaxf(e, f)));
        }
        #pragma unroll
        for (int p = 8; p < 16; p++) {
            float a, c, e, f;
            unpack2(zA[p], a, c);
            unpack2(zB[p], e, f);
            sv[p - 8] += (fmaxf(a, 0.f) + fmaxf(c, 0.f)) + (fmaxf(e, 0.f) + fmaxf(f, 0.f));
        }
    }

    // ---------------- reductions ----------------
    #pragma unroll
    for (int off = 16; off; off >>= 1) {
        #pragma unroll
        for (int p = 0; p < 8; p++) {
            mx[p] = fmaxf(mx[p], __shfl_xor_sync(0xffffffffu, mx[p], off));
            sv[p] += __shfl_xor_sync(0xffffffffu, sv[p], off);
        }
    }
    if (lane == 0) {
        #pragma unroll
        for (int p = 0; p < 8; p++) {
            sRed[w][p]     = mx[p];
            sRed[w][8 + p] = sv[p];
        }
    }
    __syncthreads();
    if (tid < 16) {
        float r;
        if (tid < 8) {
            r = sRed[0][tid];
            #pragma unroll
            for (int ww = 1; ww < 8; ww++) r = fmaxf(r, sRed[ww][tid]);
        } else {
            r = 0.f;
            #pragma unroll
            for (int ww = 0; ww < 8; ww++) r += sRed[ww][tid];
            r *= (1.0f / 16384.0f);
        }
        out[bx * 16 + tid] = r;
    }
}

extern "C" void kernel_launch(void* const* d_in, const int* in_sizes, int n_in,
                              void* d_out, int out_size)
{
    const float* x  = (const float*)d_in[0];
    const float* x1 = (const float*)d_in[1];
    const float* x2 = (const float*)d_in[2];
    const float* W1 = (const float*)d_in[3];
    const float* b1 = (const float*)d_in[4];
    const float* W2 = (const float*)d_in[5];
    const float* b2 = (const float*)d_in[6];

    const int grid = in_sizes[0] / 16;   // B*N = 512
    ppr3_kernel<<<grid, 256>>>(x, x1, x2, W1, b1, W2, b2, (float*)d_out);
}

// round 7
// speedup vs baseline: 1.0605x; 1.0605x over previous
#include <cuda_runtime.h>

typedef unsigned long long u64;
#define DINL __device__ __forceinline__

DINL u64 pack2(float lo, float hi) {
    u64 r;
    asm("mov.b64 %0, {%1, %2};" : "=l"(r) : "r"(__float_as_uint(lo)), "r"(__float_as_uint(hi)));
    return r;
}
DINL void unpack2(u64 v, float& lo, float& hi) {
    unsigned int a, b;
    asm("mov.b64 {%0, %1}, %2;" : "=r"(a), "=r"(b) : "l"(v));
    lo = __uint_as_float(a);
    hi = __uint_as_float(b);
}
DINL u64 fma2(u64 a, u64 b, u64 c) {
    u64 d;
    asm("fma.rn.f32x2 %0, %1, %2, %3;" : "=l"(d) : "l"(a), "l"(b), "l"(c));
    return d;
}

// Shapes: B=2, N=256, N1=N2=128, C=Co=16.
// h[b,n,j,k,o] = relu(base[b,n,o] + U[b,j,o] + V[b,k,o])
//   base = x.(Wa-Wb-Wc) + b1 ;  U = x1.Wb ;  V = x2.Wc
// h2 = relu(h @ W2 + b2); out = concat(max_{j,k} h2[:,:8], mean_{j,k} h2[:,8:])
//
// R5 structure (pack accumulators over p-pairs, 2-k tile, unroll-2 o-loop;
// no spills) slimmed to fit 3 CTAs/SM: U read per-o from SMEM (scalar
// broadcast), pooling accumulators live in a conflict-free SMEM slab.

__global__ void __launch_bounds__(256, 3)
ppr3_kernel(const float* __restrict__ x, const float* __restrict__ x1,
            const float* __restrict__ x2, const float* __restrict__ W1,
            const float* __restrict__ b1, const float* __restrict__ W2,
            const float* __restrict__ b2, float* __restrict__ out)
{
    __shared__ __align__(16) float  sU[128][16];    // base + U[j][o]          (8 KB)
    __shared__ __align__(16) float2 sVp[16][64];    // [o][g*32+l] = {V[64g+l],V[64g+l+32]} (8 KB)
    __shared__ __align__(16) u64    sW2p[16][8];    // W2 row o, packed p-pairs (1 KB)
    __shared__ u64   sB2p[8];
    __shared__ float sBase[16];
    __shared__ float sMx[8][256];                   // max-pool acc per thread (8 KB)
    __shared__ float sSv[8][256];                   // sum acc per thread      (8 KB)
    __shared__ float sRed[8][16];

    const int bx   = blockIdx.x;     // b*256 + n
    const int b    = bx >> 8;
    const int tid  = threadIdx.x;
    const int lane = tid & 31;
    const int w    = tid >> 5;

    // ---------------- setup ----------------
    #pragma unroll
    for (int p = 0; p < 8; p++) { sMx[p][tid] = 0.f; sSv[p][tid] = 0.f; }  // relu(max)=max(0,..)

    if (tid < 128) {
        int o = tid >> 3, pp = tid & 7;
        sW2p[o][pp] = pack2(W2[o * 16 + 2 * pp], W2[o * 16 + 2 * pp + 1]);
    } else if (tid < 136) {
        int pp = tid - 128;
        sB2p[pp] = pack2(b2[2 * pp], b2[2 * pp + 1]);
    } else if (tid < 152) {
        int o = tid - 136;
        float s = b1[o];
        const float* xr = x + bx * 16;
        #pragma unroll
        for (int c = 0; c < 16; c++)
            s += xr[c] * (W1[c * 16 + o] - W1[(16 + c) * 16 + o] - W1[(32 + c) * 16 + o]);
        sBase[o] = s;
    }

    // V pairs: [o][g*32+l] = {V[64g+l][o], V[64g+l+32][o]}
    {
        const float* x2b = x2 + b * 2048;
        for (int idx = tid; idx < 1024; idx += 256) {
            int o = idx >> 6, kk = idx & 63;
            int g = kk >> 5, l = kk & 31;
            int klo = 64 * g + l, khi = klo + 32;
            const float* rlo = x2b + klo * 16;
            const float* rhi = x2b + khi * 16;
            float slo = 0.f, shi = 0.f;
            #pragma unroll
            for (int c = 0; c < 16; c++) {
                float wv = W1[(32 + c) * 16 + o];
                slo += rlo[c] * wv;
                shi += rhi[c] * wv;
            }
            sVp[o][kk] = make_float2(slo, shi);
        }
    }
    __syncthreads();

    // U with base folded
    {
        const float* x1b = x1 + b * 2048;
        for (int idx = tid; idx < 2048; idx += 256) {
            int j = idx >> 4, o = idx & 15;
            float s = sBase[o];
            const float* xr = x1b + j * 16;
            #pragma unroll
            for (int c = 0; c < 16; c++) s += xr[c] * W1[(16 + c) * 16 + o];
            sU[j][o] = s;
        }
    }
    __syncthreads();

    // ---------------- main loop ----------------
    #pragma unroll 1
    for (int jj = 0; jj < 16; jj++) {
        const float* ujrow = sU[(w << 4) + jj];

        #pragma unroll 1
        for (int g = 0; g < 2; g++) {
            u64 z0[8], z1[8];
            #pragma unroll
            for (int pp = 0; pp < 8; pp++) {
                u64 bb = sB2p[pp];
                z0[pp] = bb; z1[pp] = bb;
            }

            #pragma unroll 2
            for (int o = 0; o < 16; o++) {
                float uo = ujrow[o];                   // LDS.32 broadcast
                float2 v = sVp[o][(g << 5) + lane];    // LDS.64 conflict-free
                float t0 = fmaxf(uo + v.x, 0.f);
                float t1 = fmaxf(uo + v.y, 0.f);
                u64 d0 = pack2(t0, t0);
                u64 d1 = pack2(t1, t1);

                const ulonglong2* wrow = reinterpret_cast<const ulonglong2*>(sW2p[o]);
                #pragma unroll
                for (int q = 0; q < 4; q++) {
                    ulonglong2 wq = wrow[q];           // LDS.128 broadcast
                    int pp = 2 * q;
                    z0[pp]     = fma2(d0, wq.x, z0[pp]);
                    z1[pp]     = fma2(d1, wq.x, z1[pp]);
                    z0[pp + 1] = fma2(d0, wq.y, z0[pp + 1]);
                    z1[pp + 1] = fma2(d1, wq.y, z1[pp + 1]);
                }
            }

            // epilogue into SMEM accumulators ([p][tid]: stride-1 per lane, no conflicts)
            #pragma unroll
            for (int pp = 0; pp < 4; pp++) {
                float a, c, e, f;
                unpack2(z0[pp], a, c);
                unpack2(z1[pp], e, f);
                sMx[2 * pp][tid]     = fmaxf(sMx[2 * pp][tid],     fmaxf(a, e));
                sMx[2 * pp + 1][tid] = fmaxf(sMx[2 * pp + 1][tid], fmaxf(c, f));
            }
            #pragma unroll
            for (int pp = 4; pp < 8; pp++) {
                float a, c, e, f;
                unpack2(z0[pp], a, c);
                unpack2(z1[pp], e, f);
                sSv[2 * (pp - 4)][tid]     += fmaxf(a, 0.f) + fmaxf(e, 0.f);
                sSv[2 * (pp - 4) + 1][tid] += fmaxf(c, 0.f) + fmaxf(f, 0.f);
            }
        }
    }

    // ---------------- reductions ----------------
    float mx[8], sv[8];
    #pragma unroll
    for (int p = 0; p < 8; p++) { mx[p] = sMx[p][tid]; sv[p] = sSv[p][tid]; }

    #pragma unroll
    for (int off = 16; off; off >>= 1) {
        #pragma unroll
        for (int p = 0; p < 8; p++) {
            mx[p] = fmaxf(mx[p], __shfl_xor_sync(0xffffffffu, mx[p], off));
            sv[p] += __shfl_xor_sync(0xffffffffu, sv[p], off);
        }
    }
    if (lane == 0) {
        #pragma unroll
        for (int p = 0; p < 8; p++) {
            sRed[w][p]     = mx[p];
            sRed[w][8 + p] = sv[p];
        }
    }
    __syncthreads();
    if (tid < 16) {
        float r;
        if (tid < 8) {
            r = sRed[0][tid];
            #pragma unroll
            for (int ww = 1; ww < 8; ww++) r = fmaxf(r, sRed[ww][tid]);
        } else {
            r = 0.f;
            #pragma unroll
            for (int ww = 0; ww < 8; ww++) r += sRed[ww][tid];
            r *= (1.0f / 16384.0f);
        }
        out[bx * 16 + tid] = r;
    }
}

extern "C" void kernel_launch(void* const* d_in, const int* in_sizes, int n_in,
                              void* d_out, int out_size)
{
    const float* x  = (const float*)d_in[0];
    const float* x1 = (const float*)d_in[1];
    const float* x2 = (const float*)d_in[2];
    const float* W1 = (const float*)d_in[3];
    const float* b1 = (const float*)d_in[4];
    const float* W2 = (const float*)d_in[5];
    const float* b2 = (const float*)d_in[6];

    const int grid = in_sizes[0] / 16;   // B*N = 512
    ppr3_kernel<<<grid, 256>>>(x, x1, x2, W1, b1, W2, b2, (float*)d_out);
}

// round 8
// speedup vs baseline: 1.1548x; 1.0889x over previous
#include <cuda_runtime.h>

typedef unsigned long long u64;
#define DINL __device__ __forceinline__

DINL u64 pack2(float lo, float hi) {
    u64 r;
    asm("mov.b64 %0, {%1, %2};" : "=l"(r) : "r"(__float_as_uint(lo)), "r"(__float_as_uint(hi)));
    return r;
}
DINL void unpack2(u64 v, float& lo, float& hi) {
    unsigned int a, b;
    asm("mov.b64 {%0, %1}, %2;" : "=r"(a), "=r"(b) : "l"(v));
    lo = __uint_as_float(a);
    hi = __uint_as_float(b);
}
DINL u64 fma2(u64 a, u64 b, u64 c) {
    u64 d;
    asm("fma.rn.f32x2 %0, %1, %2, %3;" : "=l"(d) : "l"(a), "l"(b), "l"(c));
    return d;
}

// Shapes: B=2, N=256, N1=N2=128, C=Co=16.
// h[b,n,j,k,o] = relu(base[b,n,o] + U[b,j,o] + V[b,k,o])
//   base = x.(Wa-Wb-Wc) + b1 ;  U = x1.Wb ;  V = x2.Wc
// h2 = relu(h @ W2 + b2); out = concat(max_{j,k} h2[:,:8], mean_{j,k} h2[:,8:])
//
// Crossbar-bandwidth optimized: the W2 row broadcast (2 KB delivered/warp per o)
// is amortized over a 2-j x 2-k tile (32 FFMA2 per o instead of 16).
// Block = one (b,n). Warp w owns j in [16w,16w+16), processed in pairs.
// For g in {0,1}, lane owns k-pair {64g+lane, 64g+lane+32}.
// z[j][k] packed over p-pairs: 4 x 8 u64 = 64 regs.

__global__ void __launch_bounds__(256, 2)
ppr3_kernel(const float* __restrict__ x, const float* __restrict__ x1,
            const float* __restrict__ x2, const float* __restrict__ W1,
            const float* __restrict__ b1, const float* __restrict__ W2,
            const float* __restrict__ b2, float* __restrict__ out)
{
    __shared__ __align__(16) float  sU[128][16];   // base + U[j][o]          (8 KB)
    __shared__ __align__(16) float2 sVp[16][64];   // [o][g*32+l] = {V[64g+l],V[64g+l+32]} (8 KB)
    __shared__ __align__(16) u64    sW2p[16][8];   // W2 row o, packed p-pairs (1 KB)
    __shared__ u64   sB2p[8];
    __shared__ float sBase[16];
    __shared__ float sRed[8][16];

    const int bx   = blockIdx.x;     // b*256 + n
    const int b    = bx >> 8;
    const int tid  = threadIdx.x;
    const int lane = tid & 31;
    const int w    = tid >> 5;

    // ---------------- setup ----------------
    if (tid < 128) {
        int o = tid >> 3, pp = tid & 7;
        sW2p[o][pp] = pack2(W2[o * 16 + 2 * pp], W2[o * 16 + 2 * pp + 1]);
    } else if (tid < 136) {
        int pp = tid - 128;
        sB2p[pp] = pack2(b2[2 * pp], b2[2 * pp + 1]);
    } else if (tid < 152) {
        int o = tid - 136;
        float s = b1[o];
        const float* xr = x + bx * 16;
        #pragma unroll
        for (int c = 0; c < 16; c++)
            s += xr[c] * (W1[c * 16 + o] - W1[(16 + c) * 16 + o] - W1[(32 + c) * 16 + o]);
        sBase[o] = s;
    }

    // V pairs: [o][g*32+l] = {V[64g+l][o], V[64g+l+32][o]}
    {
        const float* x2b = x2 + b * 2048;
        for (int idx = tid; idx < 1024; idx += 256) {
            int o = idx >> 6, kk = idx & 63;
            int g = kk >> 5, l = kk & 31;
            int klo = 64 * g + l, khi = klo + 32;
            const float* rlo = x2b + klo * 16;
            const float* rhi = x2b + khi * 16;
            float slo = 0.f, shi = 0.f;
            #pragma unroll
            for (int c = 0; c < 16; c++) {
                float wv = W1[(32 + c) * 16 + o];
                slo += rlo[c] * wv;
                shi += rhi[c] * wv;
            }
            sVp[o][kk] = make_float2(slo, shi);
        }
    }
    __syncthreads();

    // U with base folded
    {
        const float* x1b = x1 + b * 2048;
        for (int idx = tid; idx < 2048; idx += 256) {
            int j = idx >> 4, o = idx & 15;
            float s = sBase[o];
            const float* xr = x1b + j * 16;
            #pragma unroll
            for (int c = 0; c < 16; c++) s += xr[c] * W1[(16 + c) * 16 + o];
            sU[j][o] = s;
        }
    }
    __syncthreads();

    // ---------------- main loop ----------------
    float mx[8], sv[8];
    #pragma unroll
    for (int p = 0; p < 8; p++) { mx[p] = 0.f; sv[p] = 0.f; }  // relu(max)=max(0,..)

    #pragma unroll 1
    for (int jj = 0; jj < 8; jj++) {
        const float* u0row = sU[(w << 4) + 2 * jj];
        const float* u1row = sU[(w << 4) + 2 * jj + 1];

        #pragma unroll 1
        for (int g = 0; g < 2; g++) {
            // z[j][k][pp]: j0k0, j0k1, j1k0, j1k1
            u64 z00[8], z01[8], z10[8], z11[8];
            #pragma unroll
            for (int pp = 0; pp < 8; pp++) {
                u64 bb = sB2p[pp];
                z00[pp] = bb; z01[pp] = bb; z10[pp] = bb; z11[pp] = bb;
            }

            #pragma unroll 2
            for (int o = 0; o < 16; o++) {
                float uo0 = u0row[o];                  // LDS.32 broadcast
                float uo1 = u1row[o];                  // LDS.32 broadcast
                float2 v  = sVp[o][(g << 5) + lane];   // LDS.64 conflict-free
                float t00 = fmaxf(uo0 + v.x, 0.f);
                float t01 = fmaxf(uo0 + v.y, 0.f);
                float t10 = fmaxf(uo1 + v.x, 0.f);
                float t11 = fmaxf(uo1 + v.y, 0.f);
                u64 d00 = pack2(t00, t00);
                u64 d01 = pack2(t01, t01);
                u64 d10 = pack2(t10, t10);
                u64 d11 = pack2(t11, t11);

                const ulonglong2* wrow = reinterpret_cast<const ulonglong2*>(sW2p[o]);
                #pragma unroll
                for (int q = 0; q < 4; q++) {
                    ulonglong2 wq = wrow[q];           // LDS.128 broadcast, serves 8 FFMA2
                    int pp = 2 * q;
                    z00[pp]     = fma2(d00, wq.x, z00[pp]);
                    z01[pp]     = fma2(d01, wq.x, z01[pp]);
                    z10[pp]     = fma2(d10, wq.x, z10[pp]);
                    z11[pp]     = fma2(d11, wq.x, z11[pp]);
                    z00[pp + 1] = fma2(d00, wq.y, z00[pp + 1]);
                    z01[pp + 1] = fma2(d01, wq.y, z01[pp + 1]);
                    z10[pp + 1] = fma2(d10, wq.y, z10[pp + 1]);
                    z11[pp + 1] = fma2(d11, wq.y, z11[pp + 1]);
                }
            }

            // epilogue: pp<4 -> max pool (p 0..7); pp>=4 -> sum of relu (p 8..15)
            #pragma unroll
            for (int pp = 0; pp < 4; pp++) {
                float a0, a1, b0, b1c, c0, c1, e0, e1;
                unpack2(z00[pp], a0, a1);
                unpack2(z01[pp], b0, b1c);
                unpack2(z10[pp], c0, c1);
                unpack2(z11[pp], e0, e1);
                mx[2 * pp]     = fmaxf(mx[2 * pp],     fmaxf(fmaxf(a0, b0), fmaxf(c0, e0)));
                mx[2 * pp + 1] = fmaxf(mx[2 * pp + 1], fmaxf(fmaxf(a1, b1c), fmaxf(c1, e1)));
            }
            #pragma unroll
            for (int pp = 4; pp < 8; pp++) {
                float a0, a1, b0, b1c, c0, c1, e0, e1;
                unpack2(z00[pp], a0, a1);
                unpack2(z01[pp], b0, b1c);
                unpack2(z10[pp], c0, c1);
                unpack2(z11[pp], e0, e1);
                sv[2 * (pp - 4)]     += (fmaxf(a0, 0.f) + fmaxf(b0, 0.f))
                                      + (fmaxf(c0, 0.f) + fmaxf(e0, 0.f));
                sv[2 * (pp - 4) + 1] += (fmaxf(a1, 0.f) + fmaxf(b1c, 0.f))
                                      + (fmaxf(c1, 0.f) + fmaxf(e1, 0.f));
            }
        }
    }

    // ---------------- reductions ----------------
    #pragma unroll
    for (int off = 16; off; off >>= 1) {
        #pragma unroll
        for (int p = 0; p < 8; p++) {
            mx[p] = fmaxf(mx[p], __shfl_xor_sync(0xffffffffu, mx[p], off));
            sv[p] += __shfl_xor_sync(0xffffffffu, sv[p], off);
        }
    }
    if (lane == 0) {
        #pragma unroll
        for (int p = 0; p < 8; p++) {
            sRed[w][p]     = mx[p];
            sRed[w][8 + p] = sv[p];
        }
    }
    __syncthreads();
    if (tid < 16) {
        float r;
        if (tid < 8) {
            r = sRed[0][tid];
            #pragma unroll
            for (int ww = 1; ww < 8; ww++) r = fmaxf(r, sRed[ww][tid]);
        } else {
            r = 0.f;
            #pragma unroll
            for (int ww = 0; ww < 8; ww++) r += sRed[ww][tid];
            r *= (1.0f / 16384.0f);
        }
        out[bx * 16 + tid] = r;
    }
}

extern "C" void kernel_launch(void* const* d_in, const int* in_sizes, int n_in,
                              void* d_out, int out_size)
{
    const float* x  = (const float*)d_in[0];
    const float* x1 = (const float*)d_in[1];
    const float* x2 = (const float*)d_in[2];
    const float* W1 = (const float*)d_in[3];
    const float* b1 = (const float*)d_in[4];
    const float* W2 = (const float*)d_in[5];
    const float* b2 = (const float*)d_in[6];

    const int grid = in_sizes[0] / 16;   // B*N = 512
    ppr3_kernel<<<grid, 256>>>(x, x1, x2, W1, b1, W2, b2, (float*)d_out);
}

// round 9
// speedup vs baseline: 1.6061x; 1.3908x over previous
#include <cuda_runtime.h>

typedef unsigned long long u64;
#define DINL __device__ __forceinline__

DINL u64 pack2(float lo, float hi) {
    u64 r;
    asm("mov.b64 %0, {%1, %2};" : "=l"(r) : "r"(__float_as_uint(lo)), "r"(__float_as_uint(hi)));
    return r;
}
DINL void unpack2(u64 v, float& lo, float& hi) {
    unsigned int a, b;
    asm("mov.b64 {%0, %1}, %2;" : "=r"(a), "=r"(b) : "l"(v));
    lo = __uint_as_float(a);
    hi = __uint_as_float(b);
}
DINL u64 fma2(u64 a, u64 b, u64 c) {
    u64 d;
    asm("fma.rn.f32x2 %0, %1, %2, %3;" : "=l"(d) : "l"(a), "l"(b), "l"(c));
    return d;
}

// Shapes: B=2, N=256, N1=N2=128, C=Co=16.
// h[b,n,j,k,o] = relu(base[b,n,o] + U[b,j,o] + V[b,k,o])
//   base = x.(Wa-Wb-Wc) + b1 ;  U = x1.Wb ;  V = x2.Wc
// h2 = relu(h @ W2 + b2); out = concat(max_{j,k} h2[:,:8], mean_{j,k} h2[:,8:])
//
// 3-kernel plan:
//  k1: precompute base (per b,n), U (per b,j), V (per b,k, packed) -> scratch
//  k2: grid 2048 = (b,n) x 4 j-quarters; R8 inner loop; partials -> scratch
//  k3: merge 4 partials per (b,n): max for p<8, mean for p>=8
// Finer grid kills the 1.73-wave tail; precompute kills per-CTA setup recompute.

__device__ float  g_base[2 * 256 * 16];
__device__ float  g_U[2 * 128 * 16];
__device__ float2 g_V[2 * 16 * 64];      // [b][o][g*32+l] = {V[64g+l], V[64g+l+32]}
__device__ float  g_part[2048 * 16];     // [(bn*4+jq)][p]

// ---------------- kernel 1: precompute ----------------
__global__ void ppr3_prep(const float* __restrict__ x, const float* __restrict__ x1,
                          const float* __restrict__ x2, const float* __restrict__ W1,
                          const float* __restrict__ b1)
{
    int t = blockIdx.x * 256 + threadIdx.x;
    for (int idx = t; idx < 8192 + 4096 + 2048; idx += 8 * 256) {
        if (idx < 8192) {                 // base[bn][o]
            int bn = idx >> 4, o = idx & 15;
            float s = b1[o];
            const float* xr = x + bn * 16;
            #pragma unroll
            for (int c = 0; c < 16; c++)
                s += xr[c] * (W1[c * 16 + o] - W1[(16 + c) * 16 + o] - W1[(32 + c) * 16 + o]);
            g_base[idx] = s;
        } else if (idx < 8192 + 4096) {   // U[b][j][o]
            int i = idx - 8192;
            int b = i >> 11, j = (i >> 4) & 127, o = i & 15;
            float s = 0.f;
            const float* xr = x1 + b * 2048 + j * 16;
            #pragma unroll
            for (int c = 0; c < 16; c++) s += xr[c] * W1[(16 + c) * 16 + o];
            g_U[i] = s;
        } else {                          // V[b][o][kk] packed pair
            int i = idx - 8192 - 4096;
            int b = i >> 10, o = (i >> 6) & 15, kk = i & 63;
            int g = kk >> 5, l = kk & 31;
            int klo = 64 * g + l, khi = klo + 32;
            const float* rlo = x2 + b * 2048 + klo * 16;
            const float* rhi = x2 + b * 2048 + khi * 16;
            float slo = 0.f, shi = 0.f;
            #pragma unroll
            for (int c = 0; c < 16; c++) {
                float wv = W1[(32 + c) * 16 + o];
                slo += rlo[c] * wv;
                shi += rhi[c] * wv;
            }
            g_V[i] = make_float2(slo, shi);
        }
    }
}

// ---------------- kernel 2: main ----------------
__global__ void __launch_bounds__(256, 2)
ppr3_main(const float* __restrict__ W2, const float* __restrict__ b2)
{
    __shared__ __align__(8)  float  sUT[16][34];   // [o][jl], padded: conflict-free, LDS.64-aligned pairs
    __shared__ __align__(16) float2 sVp[16][64];
    __shared__ __align__(16) u64    sW2p[16][8];
    __shared__ u64   sB2p[8];
    __shared__ float sRed[8][16];

    const int bx   = blockIdx.x;          // bn*4 + jq
    const int bn   = bx >> 2;
    const int jq   = bx & 3;
    const int b    = bn >> 8;
    const int tid  = threadIdx.x;
    const int lane = tid & 31;
    const int w    = tid >> 5;

    // ---- setup: plain copies from scratch ----
    if (tid < 128) {
        int o = tid >> 3, pp = tid & 7;
        sW2p[o][pp] = pack2(W2[o * 16 + 2 * pp], W2[o * 16 + 2 * pp + 1]);
    } else if (tid < 136) {
        int pp = tid - 128;
        sB2p[pp] = pack2(b2[2 * pp], b2[2 * pp + 1]);
    }
    {   // U rows for this j-quarter, base folded, stored transposed
        int jl = tid >> 4, o = tid & 15;   // tid<512 needed; 256 threads -> 2 rounds
        #pragma unroll
        for (int r = 0; r < 2; r++) {
            int jll = jl + r * 16;
            float v = g_U[b * 2048 + (jq * 32 + jll) * 16 + o] + g_base[bn * 16 + o];
            sUT[o][jll] = v;
        }
    }
    {   // V copy (coalesced float2)
        const float2* src = g_V + b * 1024;
        #pragma unroll
        for (int r = 0; r < 4; r++) {
            int i = tid + r * 256;
            (&sVp[0][0])[i] = src[i];
        }
    }
    __syncthreads();

    // ---- main loop: warp w owns jl in [4w, 4w+4), as 2 j-pairs ----
    float mx[8], sv[8];
    #pragma unroll
    for (int p = 0; p < 8; p++) { mx[p] = 0.f; sv[p] = 0.f; }   // relu(max)=max(0,..)

    #pragma unroll 1
    for (int jp = 0; jp < 2; jp++) {
        const int jl = (w << 2) + (jp << 1);

        #pragma unroll 1
        for (int g = 0; g < 2; g++) {
            u64 z00[8], z01[8], z10[8], z11[8];
            #pragma unroll
            for (int pp = 0; pp < 8; pp++) {
                u64 bb = sB2p[pp];
                z00[pp] = bb; z01[pp] = bb; z10[pp] = bb; z11[pp] = bb;
            }

            #pragma unroll 2
            for (int o = 0; o < 16; o++) {
                float2 u01 = *reinterpret_cast<const float2*>(&sUT[o][jl]); // LDS.64 broadcast
                float2 v   = sVp[o][(g << 5) + lane];                       // LDS.64 conflict-free
                float t00 = fmaxf(u01.x + v.x, 0.f);
                float t01 = fmaxf(u01.x + v.y, 0.f);
                float t10 = fmaxf(u01.y + v.x, 0.f);
                float t11 = fmaxf(u01.y + v.y, 0.f);
                u64 d00 = pack2(t00, t00);
                u64 d01 = pack2(t01, t01);
                u64 d10 = pack2(t10, t10);
                u64 d11 = pack2(t11, t11);

                const ulonglong2* wrow = reinterpret_cast<const ulonglong2*>(sW2p[o]);
                #pragma unroll
                for (int q = 0; q < 4; q++) {
                    ulonglong2 wq = wrow[q];          // LDS.128 broadcast, serves 8 FFMA2
                    int pp = 2 * q;
                    z00[pp]     = fma2(d00, wq.x, z00[pp]);
                    z01[pp]     = fma2(d01, wq.x, z01[pp]);
                    z10[pp]     = fma2(d10, wq.x, z10[pp]);
                    z11[pp]     = fma2(d11, wq.x, z11[pp]);
                    z00[pp + 1] = fma2(d00, wq.y, z00[pp + 1]);
                    z01[pp + 1] = fma2(d01, wq.y, z01[pp + 1]);
                    z10[pp + 1] = fma2(d10, wq.y, z10[pp + 1]);
                    z11[pp + 1] = fma2(d11, wq.y, z11[pp + 1]);
                }
            }

            // epilogue: pp<4 -> max pool (p 0..7); pp>=4 -> sum of relu (p 8..15)
            #pragma unroll
            for (int pp = 0; pp < 4; pp++) {
                float a0, a1, b0, b1c, c0, c1, e0, e1;
                unpack2(z00[pp], a0, a1);
                unpack2(z01[pp], b0, b1c);
                unpack2(z10[pp], c0, c1);
                unpack2(z11[pp], e0, e1);
                mx[2 * pp]     = fmaxf(mx[2 * pp],     fmaxf(fmaxf(a0, b0), fmaxf(c0, e0)));
                mx[2 * pp + 1] = fmaxf(mx[2 * pp + 1], fmaxf(fmaxf(a1, b1c), fmaxf(c1, e1)));
            }
            #pragma unroll
            for (int pp = 4; pp < 8; pp++) {
                float a0, a1, b0, b1c, c0, c1, e0, e1;
                unpack2(z00[pp], a0, a1);
                unpack2(z01[pp], b0, b1c);
                unpack2(z10[pp], c0, c1);
                unpack2(z11[pp], e0, e1);
                sv[2 * (pp - 4)]     += (fmaxf(a0, 0.f) + fmaxf(b0, 0.f))
                                      + (fmaxf(c0, 0.f) + fmaxf(e0, 0.f));
                sv[2 * (pp - 4) + 1] += (fmaxf(a1, 0.f) + fmaxf(b1c, 0.f))
                                      + (fmaxf(c1, 0.f) + fmaxf(e1, 0.f));
            }
        }
    }

    // ---- block reduction -> partial ----
    #pragma unroll
    for (int off = 16; off; off >>= 1) {
        #pragma unroll
        for (int p = 0; p < 8; p++) {
            mx[p] = fmaxf(mx[p], __shfl_xor_sync(0xffffffffu, mx[p], off));
            sv[p] += __shfl_xor_sync(0xffffffffu, sv[p], off);
        }
    }
    if (lane == 0) {
        #pragma unroll
        for (int p = 0; p < 8; p++) {
            sRed[w][p]     = mx[p];
            sRed[w][8 + p] = sv[p];
        }
    }
    __syncthreads();
    if (tid < 16) {
        float r;
        if (tid < 8) {
            r = sRed[0][tid];
            #pragma unroll
            for (int ww = 1; ww < 8; ww++) r = fmaxf(r, sRed[ww][tid]);
        } else {
            r = 0.f;
            #pragma unroll
            for (int ww = 0; ww < 8; ww++) r += sRed[ww][tid];
        }
        g_part[bx * 16 + tid] = r;
    }
}

// ---------------- kernel 3: merge partials ----------------
__global__ void ppr3_reduce(float* __restrict__ out)
{
    int t = blockIdx.x * 256 + threadIdx.x;   // t < 8192
    int bn = t >> 4, p = t & 15;
    const float* pr = g_part + bn * 64 + p;   // 4 partials, stride 16
    if (p < 8) {
        float r = pr[0];
        #pragma unroll
        for (int q = 1; q < 4; q++) r = fmaxf(r, pr[q * 16]);
        out[t] = r;
    } else {
        float r = pr[0] + pr[16] + pr[32] + pr[48];
        out[t] = r * (1.0f / 16384.0f);
    }
}

extern "C" void kernel_launch(void* const* d_in, const int* in_sizes, int n_in,
                              void* d_out, int out_size)
{
    const float* x  = (const float*)d_in[0];
    const float* x1 = (const float*)d_in[1];
    const float* x2 = (const float*)d_in[2];
    const float* W1 = (const float*)d_in[3];
    const float* b1 = (const float*)d_in[4];
    const float* W2 = (const float*)d_in[5];
    const float* b2 = (const float*)d_in[6];

    ppr3_prep<<<8, 256>>>(x, x1, x2, W1, b1);
    ppr3_main<<<2048, 256>>>(W2, b2);
    ppr3_reduce<<<32, 256>>>((float*)d_out);
}

// round 10
// speedup vs baseline: 1.6936x; 1.0545x over previous
#include <cuda_runtime.h>

typedef unsigned long long u64;
#define DINL __device__ __forceinline__

DINL u64 pack2(float lo, float hi) {
    u64 r;
    asm("mov.b64 %0, {%1, %2};" : "=l"(r) : "r"(__float_as_uint(lo)), "r"(__float_as_uint(hi)));
    return r;
}
DINL void unpack2(u64 v, float& lo, float& hi) {
    unsigned int a, b;
    asm("mov.b64 {%0, %1}, %2;" : "=r"(a), "=r"(b) : "l"(v));
    lo = __uint_as_float(a);
    hi = __uint_as_float(b);
}
DINL u64 fma2(u64 a, u64 b, u64 c) {
    u64 d;
    asm("fma.rn.f32x2 %0, %1, %2, %3;" : "=l"(d) : "l"(a), "l"(b), "l"(c));
    return d;
}

// Shapes: B=2, N=256, N1=N2=128, C=Co=16.
// h[b,n,j,k,o] = relu(base[b,n,o] + U[b,j,o] + V[b,k,o])
//   base = x.(Wa-Wb-Wc) + b1 ;  U = x1.Wb ;  V = x2.Wc
// h2 = relu(h @ W2 + b2); out = concat(max_{j,k} h2[:,:8], mean_{j,k} h2[:,8:])
//
// 3-kernel plan:
//  k1: precompute base/U/V -> scratch. Grid 56: ONE item per thread (R9's
//      grid-8 version serialized 7 LDG-chain items per thread -> 14.5us).
//  k2: grid 2048 = (b,n) x 4 j-quarters; partials -> scratch  (unchanged R9)
//  k3: merge 4 partials per (b,n)                             (unchanged R9)

__device__ float  g_base[2 * 256 * 16];
__device__ float  g_U[2 * 128 * 16];
__device__ float2 g_V[2 * 16 * 64];      // [b][o][g*32+l] = {V[64g+l], V[64g+l+32]}
__device__ float  g_part[2048 * 16];     // [(bn*4+jq)][p]

// ---------------- kernel 1: precompute (1 item / thread) ----------------
__global__ void ppr3_prep(const float* __restrict__ x, const float* __restrict__ x1,
                          const float* __restrict__ x2, const float* __restrict__ W1,
                          const float* __restrict__ b1)
{
    int idx = blockIdx.x * 256 + threadIdx.x;    // < 14336 = 56*256
    if (idx < 8192) {                 // base[bn][o]
        int bn = idx >> 4, o = idx & 15;
        float s = b1[o];
        const float* xr = x + bn * 16;
        #pragma unroll
        for (int c = 0; c < 16; c++)
            s += xr[c] * (W1[c * 16 + o] - W1[(16 + c) * 16 + o] - W1[(32 + c) * 16 + o]);
        g_base[idx] = s;
    } else if (idx < 8192 + 4096) {   // U[b][j][o]
        int i = idx - 8192;
        int b = i >> 11, j = (i >> 4) & 127, o = i & 15;
        float s = 0.f;
        const float* xr = x1 + b * 2048 + j * 16;
        #pragma unroll
        for (int c = 0; c < 16; c++) s += xr[c] * W1[(16 + c) * 16 + o];
        g_U[i] = s;
    } else {                          // V[b][o][kk] packed pair
        int i = idx - 8192 - 4096;
        int b = i >> 10, o = (i >> 6) & 15, kk = i & 63;
        int g = kk >> 5, l = kk & 31;
        int klo = 64 * g + l, khi = klo + 32;
        const float* rlo = x2 + b * 2048 + klo * 16;
        const float* rhi = x2 + b * 2048 + khi * 16;
        float slo = 0.f, shi = 0.f;
        #pragma unroll
        for (int c = 0; c < 16; c++) {
            float wv = W1[(32 + c) * 16 + o];
            slo += rlo[c] * wv;
            shi += rhi[c] * wv;
        }
        g_V[i] = make_float2(slo, shi);
    }
}

// ---------------- kernel 2: main (unchanged from R9) ----------------
__global__ void __launch_bounds__(256, 2)
ppr3_main(const float* __restrict__ W2, const float* __restrict__ b2)
{
    __shared__ __align__(8)  float  sUT[16][34];   // [o][jl], padded
    __shared__ __align__(16) float2 sVp[16][64];
    __shared__ __align__(16) u64    sW2p[16][8];
    __shared__ u64   sB2p[8];
    __shared__ float sRed[8][16];

    const int bx   = blockIdx.x;          // bn*4 + jq
    const int bn   = bx >> 2;
    const int jq   = bx & 3;
    const int b    = bn >> 8;
    const int tid  = threadIdx.x;
    const int lane = tid & 31;
    const int w    = tid >> 5;

    if (tid < 128) {
        int o = tid >> 3, pp = tid & 7;
        sW2p[o][pp] = pack2(W2[o * 16 + 2 * pp], W2[o * 16 + 2 * pp + 1]);
    } else if (tid < 136) {
        int pp = tid - 128;
        sB2p[pp] = pack2(b2[2 * pp], b2[2 * pp + 1]);
    }
    {   // U rows for this j-quarter, base folded, stored transposed
        int jl = tid >> 4, o = tid & 15;
        #pragma unroll
        for (int r = 0; r < 2; r++) {
            int jll = jl + r * 16;
            float v = g_U[b * 2048 + (jq * 32 + jll) * 16 + o] + g_base[bn * 16 + o];
            sUT[o][jll] = v;
        }
    }
    {   // V copy (coalesced float2)
        const float2* src = g_V + b * 1024;
        #pragma unroll
        for (int r = 0; r < 4; r++) {
            int i = tid + r * 256;
            (&sVp[0][0])[i] = src[i];
        }
    }
    __syncthreads();

    float mx[8], sv[8];
    #pragma unroll
    for (int p = 0; p < 8; p++) { mx[p] = 0.f; sv[p] = 0.f; }   // relu(max)=max(0,..)

    #pragma unroll 1
    for (int jp = 0; jp < 2; jp++) {
        const int jl = (w << 2) + (jp << 1);

        #pragma unroll 1
        for (int g = 0; g < 2; g++) {
            u64 z00[8], z01[8], z10[8], z11[8];
            #pragma unroll
            for (int pp = 0; pp < 8; pp++) {
                u64 bb = sB2p[pp];
                z00[pp] = bb; z01[pp] = bb; z10[pp] = bb; z11[pp] = bb;
            }

            #pragma unroll 2
            for (int o = 0; o < 16; o++) {
                float2 u01 = *reinterpret_cast<const float2*>(&sUT[o][jl]); // LDS.64 broadcast
                float2 v   = sVp[o][(g << 5) + lane];                       // LDS.64 conflict-free
                float t00 = fmaxf(u01.x + v.x, 0.f);
                float t01 = fmaxf(u01.x + v.y, 0.f);
                float t10 = fmaxf(u01.y + v.x, 0.f);
                float t11 = fmaxf(u01.y + v.y, 0.f);
                u64 d00 = pack2(t00, t00);
                u64 d01 = pack2(t01, t01);
                u64 d10 = pack2(t10, t10);
                u64 d11 = pack2(t11, t11);

                const ulonglong2* wrow = reinterpret_cast<const ulonglong2*>(sW2p[o]);
                #pragma unroll
                for (int q = 0; q < 4; q++) {
                    ulonglong2 wq = wrow[q];          // LDS.128 broadcast, serves 8 FFMA2
                    int pp = 2 * q;
                    z00[pp]     = fma2(d00, wq.x, z00[pp]);
                    z01[pp]     = fma2(d01, wq.x, z01[pp]);
                    z10[pp]     = fma2(d10, wq.x, z10[pp]);
                    z11[pp]     = fma2(d11, wq.x, z11[pp]);
                    z00[pp + 1] = fma2(d00, wq.y, z00[pp + 1]);
                    z01[pp + 1] = fma2(d01, wq.y, z01[pp + 1]);
                    z10[pp + 1] = fma2(d10, wq.y, z10[pp + 1]);
                    z11[pp + 1] = fma2(d11, wq.y, z11[pp + 1]);
                }
            }

            #pragma unroll
            for (int pp = 0; pp < 4; pp++) {
                float a0, a1, b0, b1c, c0, c1, e0, e1;
                unpack2(z00[pp], a0, a1);
                unpack2(z01[pp], b0, b1c);
                unpack2(z10[pp], c0, c1);
                unpack2(z11[pp], e0, e1);
                mx[2 * pp]     = fmaxf(mx[2 * pp],     fmaxf(fmaxf(a0, b0), fmaxf(c0, e0)));
                mx[2 * pp + 1] = fmaxf(mx[2 * pp + 1], fmaxf(fmaxf(a1, b1c), fmaxf(c1, e1)));
            }
            #pragma unroll
            for (int pp = 4; pp < 8; pp++) {
                float a0, a1, b0, b1c, c0, c1, e0, e1;
                unpack2(z00[pp], a0, a1);
                unpack2(z01[pp], b0, b1c);
                unpack2(z10[pp], c0, c1);
                unpack2(z11[pp], e0, e1);
                sv[2 * (pp - 4)]     += (fmaxf(a0, 0.f) + fmaxf(b0, 0.f))
                                      + (fmaxf(c0, 0.f) + fmaxf(e0, 0.f));
                sv[2 * (pp - 4) + 1] += (fmaxf(a1, 0.f) + fmaxf(b1c, 0.f))
                                      + (fmaxf(c1, 0.f) + fmaxf(e1, 0.f));
            }
        }
    }

    #pragma unroll
    for (int off = 16; off; off >>= 1) {
        #pragma unroll
        for (int p = 0; p < 8; p++) {
            mx[p] = fmaxf(mx[p], __shfl_xor_sync(0xffffffffu, mx[p], off));
            sv[p] += __shfl_xor_sync(0xffffffffu, sv[p], off);
        }
    }
    if (lane == 0) {
        #pragma unroll
        for (int p = 0; p < 8; p++) {
            sRed[w][p]     = mx[p];
            sRed[w][8 + p] = sv[p];
        }
    }
    __syncthreads();
    if (tid < 16) {
        float r;
        if (tid < 8) {
            r = sRed[0][tid];
            #pragma unroll
            for (int ww = 1; ww < 8; ww++) r = fmaxf(r, sRed[ww][tid]);
        } else {
            r = 0.f;
            #pragma unroll
            for (int ww = 0; ww < 8; ww++) r += sRed[ww][tid];
        }
        g_part[bx * 16 + tid] = r;
    }
}

// ---------------- kernel 3: merge partials (unchanged) ----------------
__global__ void ppr3_reduce(float* __restrict__ out)
{
    int t = blockIdx.x * 256 + threadIdx.x;   // t < 8192
    int bn = t >> 4, p = t & 15;
    const float* pr = g_part + bn * 64 + p;   // 4 partials, stride 16
    if (p < 8) {
        float r = pr[0];
        #pragma unroll
        for (int q = 1; q < 4; q++) r = fmaxf(r, pr[q * 16]);
        out[t] = r;
    } else {
        float r = pr[0] + pr[16] + pr[32] + pr[48];
        out[t] = r * (1.0f / 16384.0f);
    }
}

extern "C" void kernel_launch(void* const* d_in, const int* in_sizes, int n_in,
                              void* d_out, int out_size)
{
    const float* x  = (const float*)d_in[0];
    const float* x1 = (const float*)d_in[1];
    const float* x2 = (const float*)d_in[2];
    const float* W1 = (const float*)d_in[3];
    const float* b1 = (const float*)d_in[4];
    const float* W2 = (const float*)d_in[5];
    const float* b2 = (const float*)d_in[6];

    ppr3_prep<<<56, 256>>>(x, x1, x2, W1, b1);
    ppr3_main<<<2048, 256>>>(W2, b2);
    ppr3_reduce<<<32, 256>>>((float*)d_out);
}

// round 16
// speedup vs baseline: 1.7301x; 1.0215x over previous
#include <cuda_runtime.h>

typedef unsigned long long u64;
#define DINL __device__ __forceinline__

DINL u64 pack2(float lo, float hi) {
    u64 r;
    asm("mov.b64 %0, {%1, %2};" : "=l"(r) : "r"(__float_as_uint(lo)), "r"(__float_as_uint(hi)));
    return r;
}
DINL void unpack2(u64 v, float& lo, float& hi) {
    unsigned int a, b;
    asm("mov.b64 {%0, %1}, %2;" : "=r"(a), "=r"(b) : "l"(v));
    lo = __uint_as_float(a);
    hi = __uint_as_float(b);
}
DINL u64 fma2(u64 a, u64 b, u64 c) {
    u64 d;
    asm("fma.rn.f32x2 %0, %1, %2, %3;" : "=l"(d) : "l"(a), "l"(b), "l"(c));
    return d;
}
DINL u64 add2(u64 a, u64 b) {
    u64 d;
    asm("add.rn.f32x2 %0, %1, %2;" : "=l"(d) : "l"(a), "l"(b));
    return d;
}
// packed relu: 2 scalar FMNMX on the register-pair halves (max.f32x2 doesn't exist)
DINL u64 relu2(u64 v) {
    float lo, hi;
    unpack2(v, lo, hi);
    return pack2(fmaxf(lo, 0.f), fmaxf(hi, 0.f));
}

// Shapes: B=2, N=256, N1=N2=128, C=Co=16.
// h[b,n,j,k,o] = relu(base[b,n,o] + U[b,j,o] + V[b,k,o])
//   base = x.(Wa-Wb-Wc) + b1 ;  U = x1.Wb ;  V = x2.Wc
// h2 = relu(h @ W2 + b2); out = concat(max_{j,k} h2[:,:8], mean_{j,k} h2[:,8:])
//
// R10 structure + o=0 peel (z seeded by fma2 into b2, killing 64 init MOVs
// per body) + semi-packed sum epilogue (relu2 + add2 accumulation).

__device__ float  g_base[2 * 256 * 16];
__device__ float  g_U[2 * 128 * 16];
__device__ float2 g_V[2 * 16 * 64];      // [b][o][g*32+l] = {V[64g+l], V[64g+l+32]}
__device__ float  g_part[2048 * 16];     // [(bn*4+jq)][p]

// ---------------- kernel 1: precompute (1 item / thread) ----------------
__global__ void ppr3_prep(const float* __restrict__ x, const float* __restrict__ x1,
                          const float* __restrict__ x2, const float* __restrict__ W1,
                          const float* __restrict__ b1)
{
    int idx = blockIdx.x * 256 + threadIdx.x;    // < 14336 = 56*256
    if (idx < 8192) {                 // base[bn][o]
        int bn = idx >> 4, o = idx & 15;
        float s = b1[o];
        const float* xr = x + bn * 16;
        #pragma unroll
        for (int c = 0; c < 16; c++)
            s += xr[c] * (W1[c * 16 + o] - W1[(16 + c) * 16 + o] - W1[(32 + c) * 16 + o]);
        g_base[idx] = s;
    } else if (idx < 8192 + 4096) {   // U[b][j][o]
        int i = idx - 8192;
        int b = i >> 11, j = (i >> 4) & 127, o = i & 15;
        float s = 0.f;
        const float* xr = x1 + b * 2048 + j * 16;
        #pragma unroll
        for (int c = 0; c < 16; c++) s += xr[c] * W1[(16 + c) * 16 + o];
        g_U[i] = s;
    } else {                          // V[b][o][kk] packed pair
        int i = idx - 8192 - 4096;
        int b = i >> 10, o = (i >> 6) & 15, kk = i & 63;
        int g = kk >> 5, l = kk & 31;
        int klo = 64 * g + l, khi = klo + 32;
        const float* rlo = x2 + b * 2048 + klo * 16;
        const float* rhi = x2 + b * 2048 + khi * 16;
        float slo = 0.f, shi = 0.f;
        #pragma unroll
        for (int c = 0; c < 16; c++) {
            float wv = W1[(32 + c) * 16 + o];
            slo += rlo[c] * wv;
            shi += rhi[c] * wv;
        }
        g_V[i] = make_float2(slo, shi);
    }
}

// ---------------- kernel 2: main ----------------
__global__ void __launch_bounds__(256, 2)
ppr3_main(const float* __restrict__ W2, const float* __restrict__ b2)
{
    __shared__ __align__(8)  float  sUT[16][34];   // [o][jl], padded
    __shared__ __align__(16) float2 sVp[16][64];
    __shared__ __align__(16) u64    sW2p[16][8];
    __shared__ u64   sB2p[8];
    __shared__ float sRed[8][16];

    const int bx   = blockIdx.x;          // bn*4 + jq
    const int bn   = bx >> 2;
    const int jq   = bx & 3;
    const int b    = bn >> 8;
    const int tid  = threadIdx.x;
    const int lane = tid & 31;
    const int w    = tid >> 5;

    if (tid < 128) {
        int o = tid >> 3, pp = tid & 7;
        sW2p[o][pp] = pack2(W2[o * 16 + 2 * pp], W2[o * 16 + 2 * pp + 1]);
    } else if (tid < 136) {
        int pp = tid - 128;
        sB2p[pp] = pack2(b2[2 * pp], b2[2 * pp + 1]);
    }
    {   // U rows for this j-quarter, base folded, stored transposed
        int jl = tid >> 4, o = tid & 15;
        #pragma unroll
        for (int r = 0; r < 2; r++) {
            int jll = jl + r * 16;
            float v = g_U[b * 2048 + (jq * 32 + jll) * 16 + o] + g_base[bn * 16 + o];
            sUT[o][jll] = v;
        }
    }
    {   // V copy (coalesced float2)
        const float2* src = g_V + b * 1024;
        #pragma unroll
        for (int r = 0; r < 4; r++) {
            int i = tid + r * 256;
            (&sVp[0][0])[i] = src[i];
        }
    }
    __syncthreads();

    float mx[8];
    u64   sv2[4];
    const u64 zero2 = pack2(0.f, 0.f);
    #pragma unroll
    for (int p = 0; p < 8; p++) mx[p] = 0.f;            // relu(max)=max(0,..)
    #pragma unroll
    for (int i = 0; i < 4; i++) sv2[i] = zero2;

    #pragma unroll 1
    for (int jp = 0; jp < 2; jp++) {
        const int jl = (w << 2) + (jp << 1);

        #pragma unroll 1
        for (int g = 0; g < 2; g++) {
            u64 z00[8], z01[8], z10[8], z11[8];

            // ---- o = 0 peeled: z = t*w + b2 (no init MOVs) ----
            {
                float2 u01 = *reinterpret_cast<const float2*>(&sUT[0][jl]);
                float2 v   = sVp[0][(g << 5) + lane];
                float t00 = fmaxf(u01.x + v.x, 0.f);
                float t01 = fmaxf(u01.x + v.y, 0.f);
                float t10 = fmaxf(u01.y + v.x, 0.f);
                float t11 = fmaxf(u01.y + v.y, 0.f);
                u64 d00 = pack2(t00, t00);
                u64 d01 = pack2(t01, t01);
                u64 d10 = pack2(t10, t10);
                u64 d11 = pack2(t11, t11);
                const ulonglong2* wrow = reinterpret_cast<const ulonglong2*>(sW2p[0]);
                #pragma unroll
                for (int q = 0; q < 4; q++) {
                    ulonglong2 wq = wrow[q];
                    int pp = 2 * q;
                    u64 ba = sB2p[pp], bb = sB2p[pp + 1];
                    z00[pp]     = fma2(d00, wq.x, ba);
                    z01[pp]     = fma2(d01, wq.x, ba);
                    z10[pp]     = fma2(d10, wq.x, ba);
                    z11[pp]     = fma2(d11, wq.x, ba);
                    z00[pp + 1] = fma2(d00, wq.y, bb);
                    z01[pp + 1] = fma2(d01, wq.y, bb);
                    z10[pp + 1] = fma2(d10, wq.y, bb);
                    z11[pp + 1] = fma2(d11, wq.y, bb);
                }
            }

            // ---- o = 1..15 ----
            #pragma unroll 2
            for (int o = 1; o < 16; o++) {
                float2 u01 = *reinterpret_cast<const float2*>(&sUT[o][jl]); // LDS.64 broadcast
                float2 v   = sVp[o][(g << 5) + lane];                       // LDS.64 conflict-free
                float t00 = fmaxf(u01.x + v.x, 0.f);
                float t01 = fmaxf(u01.x + v.y, 0.f);
                float t10 = fmaxf(u01.y + v.x, 0.f);
                float t11 = fmaxf(u01.y + v.y, 0.f);
                u64 d00 = pack2(t00, t00);
                u64 d01 = pack2(t01, t01);
                u64 d10 = pack2(t10, t10);
                u64 d11 = pack2(t11, t11);

                const ulonglong2* wrow = reinterpret_cast<const ulonglong2*>(sW2p[o]);
                #pragma unroll
                for (int q = 0; q < 4; q++) {
                    ulonglong2 wq = wrow[q];          // LDS.128 broadcast, serves 8 FFMA2
                    int pp = 2 * q;
                    z00[pp]     = fma2(d00, wq.x, z00[pp]);
                    z01[pp]     = fma2(d01, wq.x, z01[pp]);
                    z10[pp]     = fma2(d10, wq.x, z10[pp]);
                    z11[pp]     = fma2(d11, wq.x, z11[pp]);
                    z00[pp + 1] = fma2(d00, wq.y, z00[pp + 1]);
                    z01[pp + 1] = fma2(d01, wq.y, z01[pp + 1]);
                    z10[pp + 1] = fma2(d10, wq.y, z10[pp + 1]);
                    z11[pp + 1] = fma2(d11, wq.y, z11[pp + 1]);
                }
            }

            // ---- epilogue ----
            // pp<4: max pool (scalar — no packed max on sm_103a)
            #pragma unroll
            for (int pp = 0; pp < 4; pp++) {
                float a0, a1, b0, b1c, c0, c1, e0, e1;
                unpack2(z00[pp], a0, a1);
                unpack2(z01[pp], b0, b1c);
                unpack2(z10[pp], c0, c1);
                unpack2(z11[pp], e0, e1);
                mx[2 * pp]     = fmaxf(mx[2 * pp],     fmaxf(fmaxf(a0, b0), fmaxf(c0, e0)));
                mx[2 * pp + 1] = fmaxf(mx[2 * pp + 1], fmaxf(fmaxf(a1, b1c), fmaxf(c1, e1)));
            }
            // pp>=4: sum of relu, packed accumulation
            #pragma unroll
            for (int pp = 4; pp < 8; pp++) {
                u64 r0 = add2(relu2(z00[pp]), relu2(z01[pp]));
                u64 r1 = add2(relu2(z10[pp]), relu2(z11[pp]));
                sv2[pp - 4] = add2(sv2[pp - 4], add2(r0, r1));
            }
        }
    }

    // ---- unpack sums, block reduction -> partial ----
    float sv[8];
    #pragma unroll
    for (int i = 0; i < 4; i++) unpack2(sv2[i], sv[2 * i], sv[2 * i + 1]);

    #pragma unroll
    for (int off = 16; off; off >>= 1) {
        #pragma unroll
        for (int p = 0; p < 8; p++) {
            mx[p] = fmaxf(mx[p], __shfl_xor_sync(0xffffffffu, mx[p], off));
            sv[p] += __shfl_xor_sync(0xffffffffu, sv[p], off);
        }
    }
    if (lane == 0) {
        #pragma unroll
        for (int p = 0; p < 8; p++) {
            sRed[w][p]     = mx[p];
            sRed[w][8 + p] = sv[p];
        }
    }
    __syncthreads();
    if (tid < 16) {
        float r;
        if (tid < 8) {
            r = sRed[0][tid];
            #pragma unroll
            for (int ww = 1; ww < 8; ww++) r = fmaxf(r, sRed[ww][tid]);
        } else {
            r = 0.f;
            #pragma unroll
            for (int ww = 0; ww < 8; ww++) r += sRed[ww][tid];
        }
        g_part[bx * 16 + tid] = r;
    }
}

// ---------------- kernel 3: merge partials (unchanged) ----------------
__global__ void ppr3_reduce(float* __restrict__ out)
{
    int t = blockIdx.x * 256 + threadIdx.x;   // t < 8192
    int bn = t >> 4, p = t & 15;
    const float* pr = g_part + bn * 64 + p;   // 4 partials, stride 16
    if (p < 8) {
        float r = pr[0];
        #pragma unroll
        for (int q = 1; q < 4; q++) r = fmaxf(r, pr[q * 16]);
        out[t] = r;
    } else {
        float r = pr[0] + pr[16] + pr[32] + pr[48];
        out[t] = r * (1.0f / 16384.0f);
    }
}

extern "C" void kernel_launch(void* const* d_in, const int* in_sizes, int n_in,
                              void* d_out, int out_size)
{
    const float* x  = (const float*)d_in[0];
    const float* x1 = (const float*)d_in[1];
    const float* x2 = (const float*)d_in[2];
    const float* W1 = (const float*)d_in[3];
    const float* b1 = (const float*)d_in[4];
    const float* W2 = (const float*)d_in[5];
    const float* b2 = (const float*)d_in[6];

    ppr3_prep<<<56, 256>>>(x, x1, x2, W1, b1);
    ppr3_main<<<2048, 256>>>(W2, b2);
    ppr3_reduce<<<32, 256>>>((float*)d_out);
}